// round 3
// baseline (speedup 1.0000x reference)
#include <cuda_runtime.h>
#include <cstdint>

// B=4, C=256, N=1024, heads=8, dk=32, KV len = 3072
#define CN (256 * 1024)

// Scratch (__device__ globals; allocation-free rule)
__device__ float g_Q[4 * 8 * 1024 * 32];     // [b][h][q][d]  (qscale folded)
__device__ float g_K[4 * 8 * 3072 * 32];     // [b][h][kv][d]
__device__ float g_V[12 * 256 * 1024];       // [b*3+s][C][N]
__device__ float g_att[4 * 256 * 1024];      // [b][C][N]

typedef unsigned long long u64;

// ---------------- packed fp32x2 (for the projection GEMMs) ----------------
__device__ __forceinline__ u64 ffma2(u64 a, u64 b, u64 c) {
    u64 d; asm("fma.rn.f32x2 %0, %1, %2, %3;" : "=l"(d) : "l"(a), "l"(b), "l"(c));
    return d;
}
__device__ __forceinline__ float2 unpack2(u64 v) {
    float2 r; asm("mov.b64 {%0, %1}, %2;" : "=f"(r.x), "=f"(r.y) : "l"(v));
    return r;
}

// ---------------- tf32 helpers ----------------
__device__ __forceinline__ uint32_t cvt_tf32(float x) {
    uint32_t r; asm("cvt.rna.tf32.f32 %0, %1;" : "=r"(r) : "f"(x));
    return r;
}
__device__ __forceinline__ float tf32f(float x) {
    return __uint_as_float(cvt_tf32(x));
}
// D = A(16x8) * B(8x8) + C, tf32 inputs, fp32 accum
__device__ __forceinline__ void mma_tf32(float4& d, const uint32_t a[4],
                                         const uint32_t b0, const uint32_t b1,
                                         const float4& c) {
    asm("mma.sync.aligned.m16n8k8.row.col.f32.tf32.tf32.f32 "
        "{%0,%1,%2,%3}, {%4,%5,%6,%7}, {%8,%9}, {%10,%11,%12,%13};"
        : "=f"(d.x), "=f"(d.y), "=f"(d.z), "=f"(d.w)
        : "r"(a[0]), "r"(a[1]), "r"(a[2]), "r"(a[3]), "r"(b0), "r"(b1),
          "f"(c.x), "f"(c.y), "f"(c.z), "f"(c.w));
}

// ---------------------------------------------------------------------------
// SGEMM: out = W[256x256] @ (xscale*X[256x1024]) + bscale*bias
// transposed=false: write out[C][N] (row o, col n)
// transposed=true : write outT[((o>>5)*seqtot + nofs + n)*32 + (o&31)]
// ---------------------------------------------------------------------------
__device__ __forceinline__ void sgemm_256(const float* __restrict__ W,
                                          const float* __restrict__ X,
                                          const float* __restrict__ bias,
                                          float xscale, float bscale,
                                          float* __restrict__ out,
                                          bool transposed, float* __restrict__ outT,
                                          int seqtot, int nofs,
                                          int m0, int n0)
{
    __shared__ float As2[8][256];
    __shared__ float Bs[8][128];

    const int t  = threadIdx.x;
    const int tx = t & 15;
    const int ty = t >> 4;
    const int arow = t >> 1, acol = (t & 1) * 4;
    const int brow = t >> 5, bcol = (t & 31) * 4;

    u64 acc[8][4];
#pragma unroll
    for (int i = 0; i < 8; i++)
#pragma unroll
        for (int j = 0; j < 4; j++) acc[i][j] = 0ull;

    for (int k0 = 0; k0 < 256; k0 += 8) {
        float4 av = *(const float4*)(W + (m0 + arow) * 256 + k0 + acol);
        float4 bv = *(const float4*)(X + (k0 + brow) * 1024 + n0 + bcol);
        __syncthreads();
        *(float2*)&As2[acol + 0][2 * arow] = make_float2(av.x, av.x);
        *(float2*)&As2[acol + 1][2 * arow] = make_float2(av.y, av.y);
        *(float2*)&As2[acol + 2][2 * arow] = make_float2(av.z, av.z);
        *(float2*)&As2[acol + 3][2 * arow] = make_float2(av.w, av.w);
        bv.x *= xscale; bv.y *= xscale; bv.z *= xscale; bv.w *= xscale;
        *(float4*)&Bs[brow][bcol] = bv;
        __syncthreads();
#pragma unroll
        for (int k = 0; k < 8; k++) {
            ulonglong2 a0 = *(const ulonglong2*)&As2[k][16 * ty];
            ulonglong2 a1 = *(const ulonglong2*)&As2[k][16 * ty + 4];
            ulonglong2 a2 = *(const ulonglong2*)&As2[k][16 * ty + 8];
            ulonglong2 a3 = *(const ulonglong2*)&As2[k][16 * ty + 12];
            ulonglong2 b0 = *(const ulonglong2*)&Bs[k][tx * 8];
            ulonglong2 b1 = *(const ulonglong2*)&Bs[k][tx * 8 + 4];
            u64 a[8] = {a0.x, a0.y, a1.x, a1.y, a2.x, a2.y, a3.x, a3.y};
            u64 b[4] = {b0.x, b0.y, b1.x, b1.y};
#pragma unroll
            for (int i = 0; i < 8; i++)
#pragma unroll
                for (int j = 0; j < 4; j++)
                    acc[i][j] = ffma2(a[i], b[j], acc[i][j]);
        }
    }

    float v[8][8];
#pragma unroll
    for (int i = 0; i < 8; i++) {
        float bi = bias[m0 + ty * 8 + i] * bscale;
        float2 p0 = unpack2(acc[i][0]);
        float2 p1 = unpack2(acc[i][1]);
        float2 p2 = unpack2(acc[i][2]);
        float2 p3 = unpack2(acc[i][3]);
        v[i][0] = p0.x + bi; v[i][1] = p0.y + bi;
        v[i][2] = p1.x + bi; v[i][3] = p1.y + bi;
        v[i][4] = p2.x + bi; v[i][5] = p2.y + bi;
        v[i][6] = p3.x + bi; v[i][7] = p3.y + bi;
    }

    if (!transposed) {
#pragma unroll
        for (int i = 0; i < 8; i++) {
            float* orow = out + (m0 + ty * 8 + i) * 1024 + n0 + tx * 8;
            *(float4*)orow       = make_float4(v[i][0], v[i][1], v[i][2], v[i][3]);
            *(float4*)(orow + 4) = make_float4(v[i][4], v[i][5], v[i][6], v[i][7]);
        }
    } else {
        const int o0 = m0 + ty * 8;            // 8-aligned -> one head
        const int hh = o0 >> 5, d0 = o0 & 31;
        float* base = outT + ((size_t)hh * seqtot + nofs + n0 + tx * 8) * 32 + d0;
#pragma unroll
        for (int j = 0; j < 8; j++) {
            *(float4*)(base + j * 32)     = make_float4(v[0][j], v[1][j], v[2][j], v[3][j]);
            *(float4*)(base + j * 32 + 4) = make_float4(v[4][j], v[5][j], v[6][j], v[7][j]);
        }
    }
}

// QKV projections. grid = (8, 2, 28); z -> (b, which-of-7)
__global__ void __launch_bounds__(256)
gemm_qkv_kernel(const float* __restrict__ x0, const float* __restrict__ x1,
                const float* __restrict__ x2,
                const float* __restrict__ g0, const float* __restrict__ g1,
                const float* __restrict__ g2,
                const float* __restrict__ Wq, const float* __restrict__ bq,
                const float* __restrict__ Wk, const float* __restrict__ bk,
                const float* __restrict__ Wv, const float* __restrict__ bv)
{
    const int z = blockIdx.z;
    const int b = z / 7;
    const int r = z % 7;
    const float qscale = 0.1767766953f;   // 1/sqrt(32)

    int s;
    const float* W;
    const float* bias;
    float* out = nullptr;
    float* outT = nullptr;
    bool tr;
    float bscale = 1.0f;
    int seqtot = 0, nofs = 0;

    if (r == 0) {
        s = 0; W = Wq; bias = bq; tr = true;
        outT = g_Q + (size_t)b * 8 * 1024 * 32;
        seqtot = 1024; nofs = 0; bscale = qscale;
    } else if (r <= 3) {
        s = r - 1; W = Wk; bias = bk; tr = true;
        outT = g_K + (size_t)b * 8 * 3072 * 32;
        seqtot = 3072; nofs = s * 1024;
    } else {
        s = r - 4; W = Wv; bias = bv; tr = false;
        out = g_V + (size_t)(b * 3 + s) * CN;
    }

    const float* X = (s == 0 ? x0 : (s == 1 ? x1 : x2)) + (size_t)b * CN;
    float xs = (s == 0 ? g0 : (s == 1 ? g1 : g2))[0];
    if (r == 0) xs *= qscale;

    sgemm_256(W, X, bias, xs, bscale, out, tr, outT, seqtot, nofs,
              blockIdx.y * 128, blockIdx.x * 128);
}

// Output projection. grid = (8, 2, 4)
__global__ void __launch_bounds__(256)
gemm_out_kernel(const float* __restrict__ Wo, const float* __restrict__ bo,
                float* __restrict__ outp)
{
    const int b = blockIdx.z;
    sgemm_256(Wo, g_att + (size_t)b * CN, bo, 1.0f, 1.0f, outp + (size_t)b * CN,
              false, nullptr, 0, 0, blockIdx.y * 128, blockIdx.x * 128);
}

// ---------------------------------------------------------------------------
// Flash attention with tf32 mma.sync (m16n8k8).
// grid = (16 q-tiles, 8 heads, 4 batch), 128 threads (4 warps).
// q-tile 64 (warp w owns rows w*16..+15), k-tile 64, dk=32, 48 KV tiles.
// Q fragments register-resident for the whole KV loop.
// K/V staged in SMEM with k-permuted columns so fragment loads are LDS.128.
// ---------------------------------------------------------------------------
__global__ void __launch_bounds__(128)
attn_kernel()
{
    const int b  = blockIdx.z;
    const int h  = blockIdx.y;
    const int q0 = blockIdx.x * 64;

    __shared__ float Ks[64][36];   // [key][perm d],  col' = (d&3)*8  + (d>>2)
    __shared__ float Vs[32][68];   // [d][perm k],    col' = (k&3)*16 + (k>>2)
    __shared__ float Ps[64][68];   // [q][perm k]

    const int t    = threadIdx.x;
    const int w    = t >> 5;
    const int lane = t & 31;
    const int g    = lane >> 2;    // group id (row within fragment)
    const int tig  = lane & 3;     // thread in group

    // ---- Q fragments (A of S-mma), held in registers across all KV tiles
    uint32_t qa[4][4];
    {
        const float* Q0 = g_Q + ((size_t)(b * 8 + h) * 1024 + q0 + w * 16) * 32;
#pragma unroll
        for (int kf = 0; kf < 4; kf++) {
            qa[kf][0] = cvt_tf32(Q0[g * 32 + 8 * kf + tig]);
            qa[kf][1] = cvt_tf32(Q0[(g + 8) * 32 + 8 * kf + tig]);
            qa[kf][2] = cvt_tf32(Q0[g * 32 + 8 * kf + tig + 4]);
            qa[kf][3] = cvt_tf32(Q0[(g + 8) * 32 + 8 * kf + tig + 4]);
        }
    }

    float m0r = -1e30f, m1r = -1e30f, l0 = 0.f, l1 = 0.f;
    float4 o[4];
#pragma unroll
    for (int nf = 0; nf < 4; nf++) o[nf] = make_float4(0.f, 0.f, 0.f, 0.f);

    for (int kt = 0; kt < 48; kt++) {
        const float* Kg = g_K + ((size_t)(b * 8 + h) * 3072 + kt * 64) * 32;
        const int s  = kt >> 4;
        const int n0 = (kt & 15) * 64;
        const float* Vg = g_V + (size_t)(b * 3 + s) * CN + (h * 32) * 1024 + n0;

        __syncthreads();   // protect Ks/Vs from previous tile's readers

        // stage K tile: 64 rows x 32 d, tf32-rounded, permuted
        {
            const int row = t >> 1, hh = t & 1;
            const float4* src = (const float4*)(Kg + row * 32 + hh * 16);
#pragma unroll
            for (int a = 0; a < 4; a++) {
                float4 kv = src[a];
                int base = 4 * hh + a;          // col' = c*8 + 4h + a
                Ks[row][base]      = tf32f(kv.x);
                Ks[row][8 + base]  = tf32f(kv.y);
                Ks[row][16 + base] = tf32f(kv.z);
                Ks[row][24 + base] = tf32f(kv.w);
            }
        }
        // stage V tile: 32 rows (d) x 64 k, tf32-rounded, permuted
        {
            const int d = t >> 2, qq = t & 3;
            const float4* src = (const float4*)(Vg + d * 1024 + qq * 16);
#pragma unroll
            for (int a = 0; a < 4; a++) {
                float4 vv = src[a];
                int base = 4 * qq + a;          // col' = c*16 + 4q + a
                Vs[d][base]      = tf32f(vv.x);
                Vs[d][16 + base] = tf32f(vv.y);
                Vs[d][32 + base] = tf32f(vv.z);
                Vs[d][48 + base] = tf32f(vv.w);
            }
        }
        __syncthreads();

        // ---- S = Q K^T for this tile (per warp: 16 q x 64 keys)
        float4 sacc[8];
#pragma unroll
        for (int nf = 0; nf < 8; nf++) sacc[nf] = make_float4(0.f, 0.f, 0.f, 0.f);

#pragma unroll
        for (int nf = 0; nf < 8; nf++) {
            const uint32_t* kr = (const uint32_t*)&Ks[8 * nf + g][tig * 8];
            uint4 kb0 = *(const uint4*)kr;
            uint4 kb1 = *(const uint4*)(kr + 4);
            mma_tf32(sacc[nf], qa[0], kb0.x, kb0.y, sacc[nf]);
            mma_tf32(sacc[nf], qa[1], kb0.z, kb0.w, sacc[nf]);
            mma_tf32(sacc[nf], qa[2], kb1.x, kb1.y, sacc[nf]);
            mma_tf32(sacc[nf], qa[3], kb1.z, kb1.w, sacc[nf]);
        }

        // ---- online softmax; thread owns rows {g, g+8}, 16 cols each
        float mx0 = -1e30f, mx1 = -1e30f;
#pragma unroll
        for (int nf = 0; nf < 8; nf++) {
            mx0 = fmaxf(mx0, fmaxf(sacc[nf].x, sacc[nf].y));
            mx1 = fmaxf(mx1, fmaxf(sacc[nf].z, sacc[nf].w));
        }
        mx0 = fmaxf(mx0, __shfl_xor_sync(0xffffffffu, mx0, 1));
        mx0 = fmaxf(mx0, __shfl_xor_sync(0xffffffffu, mx0, 2));
        mx1 = fmaxf(mx1, __shfl_xor_sync(0xffffffffu, mx1, 1));
        mx1 = fmaxf(mx1, __shfl_xor_sync(0xffffffffu, mx1, 2));

        float mn0 = fmaxf(m0r, mx0);
        float mn1 = fmaxf(m1r, mx1);
        float r0 = __expf(m0r - mn0);
        float r1 = __expf(m1r - mn1);
        m0r = mn0; m1r = mn1;

        const int qrow = w * 16 + g;
        float sum0 = 0.f, sum1 = 0.f;
#pragma unroll
        for (int nf = 0; nf < 8; nf++) {
            int k0c = 8 * nf + 2 * tig;
            float e0 = __expf(sacc[nf].x - mn0);
            float e1 = __expf(sacc[nf].y - mn0);
            float e2 = __expf(sacc[nf].z - mn1);
            float e3 = __expf(sacc[nf].w - mn1);
            sum0 += e0 + e1;
            sum1 += e2 + e3;
            int c0 = (k0c & 3) * 16 + (k0c >> 2);
            int c1 = ((k0c + 1) & 3) * 16 + ((k0c + 1) >> 2);
            Ps[qrow][c0]     = tf32f(e0);
            Ps[qrow][c1]     = tf32f(e1);
            Ps[qrow + 8][c0] = tf32f(e2);
            Ps[qrow + 8][c1] = tf32f(e3);
        }
        sum0 += __shfl_xor_sync(0xffffffffu, sum0, 1);
        sum0 += __shfl_xor_sync(0xffffffffu, sum0, 2);
        sum1 += __shfl_xor_sync(0xffffffffu, sum1, 1);
        sum1 += __shfl_xor_sync(0xffffffffu, sum1, 2);
        l0 = l0 * r0 + sum0;
        l1 = l1 * r1 + sum1;
#pragma unroll
        for (int nf = 0; nf < 4; nf++) {
            o[nf].x *= r0; o[nf].y *= r0;
            o[nf].z *= r1; o[nf].w *= r1;
        }
        __syncwarp();   // Ps round-trip is intra-warp

        // ---- O += P V (per warp: 16 q x 32 d, K-dim = 64)
        uint32_t pa[2][16];
        {
            const uint32_t* p0 = (const uint32_t*)&Ps[qrow][tig * 16];
            const uint32_t* p1 = (const uint32_t*)&Ps[qrow + 8][tig * 16];
#pragma unroll
            for (int u = 0; u < 4; u++) {
                *(uint4*)&pa[0][4 * u] = *(const uint4*)(p0 + 4 * u);
                *(uint4*)&pa[1][4 * u] = *(const uint4*)(p1 + 4 * u);
            }
        }
#pragma unroll
        for (int nf = 0; nf < 4; nf++) {
            const uint32_t* vr = (const uint32_t*)&Vs[8 * nf + g][tig * 16];
            uint32_t vb[16];
#pragma unroll
            for (int u = 0; u < 4; u++)
                *(uint4*)&vb[4 * u] = *(const uint4*)(vr + 4 * u);
#pragma unroll
            for (int kf = 0; kf < 8; kf++) {
                uint32_t af[4] = {pa[0][2 * kf], pa[1][2 * kf],
                                  pa[0][2 * kf + 1], pa[1][2 * kf + 1]};
                mma_tf32(o[nf], af, vb[2 * kf], vb[2 * kf + 1], o[nf]);
            }
        }
    }

    // ---- normalize and write g_att[b][h*32+d][q]
    const float inv0 = 1.0f / l0;
    const float inv1 = 1.0f / l1;
    const int qrow = q0 + w * 16 + g;
#pragma unroll
    for (int nf = 0; nf < 4; nf++) {
        int d0 = 8 * nf + 2 * tig;
        float* base = g_att + (size_t)(b * 256 + h * 32 + d0) * 1024;
        base[qrow]            = o[nf].x * inv0;
        base[1024 + qrow]     = o[nf].y * inv0;
        base[qrow + 8]        = o[nf].z * inv1;
        base[1024 + qrow + 8] = o[nf].w * inv1;
    }
}

// ---------------------------------------------------------------------------
extern "C" void kernel_launch(void* const* d_in, const int* in_sizes, int n_in,
                              void* d_out, int out_size)
{
    const float* x0 = (const float*)d_in[0];
    const float* x1 = (const float*)d_in[1];
    const float* x2 = (const float*)d_in[2];
    const float* g0 = (const float*)d_in[3];
    const float* g1 = (const float*)d_in[4];
    const float* g2 = (const float*)d_in[5];
    const float* Wq = (const float*)d_in[6];
    const float* bq = (const float*)d_in[7];
    const float* Wk = (const float*)d_in[8];
    const float* bk = (const float*)d_in[9];
    const float* Wv = (const float*)d_in[10];
    const float* bv = (const float*)d_in[11];
    const float* Wo = (const float*)d_in[12];
    const float* bo = (const float*)d_in[13];
    float* outp = (float*)d_out;

    dim3 gq(8, 2, 28);
    gemm_qkv_kernel<<<gq, 256>>>(x0, x1, x2, g0, g1, g2,
                                 Wq, bq, Wk, bk, Wv, bv);

    dim3 ga(16, 8, 4);
    attn_kernel<<<ga, 128>>>();

    dim3 go(8, 2, 4);
    gemm_out_kernel<<<go, 256>>>(Wo, bo, outp);
}